// round 6
// baseline (speedup 1.0000x reference)
#include <cuda_runtime.h>

// SlowNorm: per-irrep L2 norms.
// irreps: (256,1) (256,3) (128,5) (64,7)  -> DIM=2112 in, OUT=704 out per row.
// Key fact: every output float4-chunk q (176 per row) reads a CONTIGUOUS,
// 16B-ALIGNED input span:
//   q in [0,64):    1 float4 at f4-index q            (d=1, out = |x|)
//   q in [64,128):  3 float4 at f4-index 3q-128       (d=3)
//   q in [128,160): 5 float4 at f4-index 5q-384       (d=5)
//   q in [160,176): 7 float4 at f4-index 7q-704       (d=7)
// => one thread per chunk, direct LDG.128 -> FMA -> sqrt -> STG.128.
// No shared memory, no barriers, contiguous ascending access across threads.

#define DIM       2112
#define OUT_DIM   704
#define F4_ROW    (DIM / 4)       // 528
#define Q_PER_ROW (OUT_DIM / 4)   // 176
#define THREADS   256

__device__ __forceinline__ float4 ldcs4(const float4* p) {
    float4 v;
    asm volatile("ld.global.cs.v4.f32 {%0,%1,%2,%3}, [%4];\n"
                 : "=f"(v.x), "=f"(v.y), "=f"(v.z), "=f"(v.w) : "l"(p));
    return v;
}
__device__ __forceinline__ void stcs4(float4* p, float4 v) {
    asm volatile("st.global.cs.v4.f32 [%0], {%1,%2,%3,%4};\n"
                 :: "l"(p), "f"(v.x), "f"(v.y), "f"(v.z), "f"(v.w));
}

__global__ __launch_bounds__(THREADS) void slownorm_kernel(
    const float* __restrict__ in, float* __restrict__ out)
{
    const int chunk = blockIdx.x * THREADS + threadIdx.x;   // < 65536*176, exact
    const int row = chunk / Q_PER_ROW;
    const int q   = chunk - row * Q_PER_ROW;

    const float4* __restrict__ src =
        reinterpret_cast<const float4*>(in) + (long long)row * F4_ROW;
    float4 v;

    if (q < 64) {                       // d=1: |x|
        const float4 x = ldcs4(src + q);
        v.x = fabsf(x.x); v.y = fabsf(x.y); v.z = fabsf(x.z); v.w = fabsf(x.w);
    } else if (q < 128) {               // d=3: 12 floats
        float4 r[3];
        const float4* p = src + (3 * q - 128);
        #pragma unroll
        for (int k = 0; k < 3; k++) r[k] = ldcs4(p + k);
        const float* f = reinterpret_cast<const float*>(r);
        float a[4];
        #pragma unroll
        for (int k = 0; k < 4; k++) {
            const float* e = f + 3 * k;
            float acc = e[0] * e[0];
            acc = fmaf(e[1], e[1], acc);
            acc = fmaf(e[2], e[2], acc);
            a[k] = sqrtf(acc);
        }
        v.x = a[0]; v.y = a[1]; v.z = a[2]; v.w = a[3];
    } else if (q < 160) {               // d=5: 20 floats
        float4 r[5];
        const float4* p = src + (5 * q - 384);
        #pragma unroll
        for (int k = 0; k < 5; k++) r[k] = ldcs4(p + k);
        const float* f = reinterpret_cast<const float*>(r);
        float a[4];
        #pragma unroll
        for (int k = 0; k < 4; k++) {
            const float* e = f + 5 * k;
            float acc = e[0] * e[0];
            #pragma unroll
            for (int j = 1; j < 5; j++) acc = fmaf(e[j], e[j], acc);
            a[k] = sqrtf(acc);
        }
        v.x = a[0]; v.y = a[1]; v.z = a[2]; v.w = a[3];
    } else {                            // d=7: 28 floats
        float4 r[7];
        const float4* p = src + (7 * q - 704);
        #pragma unroll
        for (int k = 0; k < 7; k++) r[k] = ldcs4(p + k);
        const float* f = reinterpret_cast<const float*>(r);
        float a[4];
        #pragma unroll
        for (int k = 0; k < 4; k++) {
            const float* e = f + 7 * k;
            float acc = e[0] * e[0];
            #pragma unroll
            for (int j = 1; j < 7; j++) acc = fmaf(e[j], e[j], acc);
            a[k] = sqrtf(acc);
        }
        v.x = a[0]; v.y = a[1]; v.z = a[2]; v.w = a[3];
    }

    stcs4(reinterpret_cast<float4*>(out) + (long long)row * Q_PER_ROW + q, v);
}

extern "C" void kernel_launch(void* const* d_in, const int* in_sizes, int n_in,
                              void* d_out, int out_size)
{
    const float* features = (const float*)d_in[0];
    float* out = (float*)d_out;
    const int batch = in_sizes[0] / DIM;            // 65536
    const long long total = (long long)batch * Q_PER_ROW;   // 11,534,336
    const int grid = (int)(total / THREADS);        // 45056, exact
    slownorm_kernel<<<grid, THREADS>>>(features, out);
}